// round 17
// baseline (speedup 1.0000x reference)
#include <cuda_runtime.h>

// Problem constants (fixed shapes)
#define T_TOK 8192
#define D_IN  1024
#define H1    128
#define QDIM  32
#define HALFD 8
#define KNN   8
#define NKEYS 256

// k1 tiling: 64 tokens x 128 outputs per block, BK=16, 128 threads (4 warps).
#define BM 64
#define BN 128
#define BK 16
#define NKT (D_IN / BK)   // 64

// smem strides (floats)
#define XS_STRIDE 68
#define WS_STRIDE 132
#define HS_STRIDE 140

#define XS_BUF (BK * XS_STRIDE)
#define WS_BUF (BK * WS_STRIDE)
#define SMEM_MAIN ((2 * XS_BUF + 2 * WS_BUF) * 4)          // 25600 B
#define SMEM_EPI  ((BM * HS_STRIDE + QDIM * H1) * 4)       // 52224 B
#define SMEM_BYTES (SMEM_EPI > SMEM_MAIN ? SMEM_EPI : SMEM_MAIN)

// Scratch (device globals: allocation-free rule)
__device__ __align__(16) float g_q[T_TOK * QDIM];   // 1 MB
__device__ float g_wt[T_TOK * 16];                  // 512 KB
__device__ int   g_id[T_TOK * 16];                  // 512 KB

// Packed dual-fp32 FMA (B300 FFMA2, rt~2)
#define FMA2(d, a, b) asm("fma.rn.f32x2 %0, %1, %2, %0;" : "+l"(d) : "l"(a), "l"(b))
#define DUP2(d, s)    asm("mov.b64 %0, {%1, %1};" : "=l"(d) : "f"(s))

extern __shared__ __align__(16) char smem_raw[];

// ---------------------------------------------------------------------------
// Kernel 1 (fused): h = relu(x@W1^T + b1); q = h@W2^T + b2 -> g_q
//   128 threads, 4 warps (2 warp-rows x 2 warp-cols), warp tile 32tok x 64col,
//   lane tile 8tok x 8col. Per k per lane: 2 broadcast a-LDS.128 +
//   2 b-LDS.128 (natural col pairs) + 8 DUP (alu) + 32 FMA2.
//   k order 0..1023 sequential per accumulator (bit-identical to prior rounds).
//   Conflict-free STS: each warp stores whole k-rows (consecutive lanes ->
//   consecutive banks).
// ---------------------------------------------------------------------------
__global__ __launch_bounds__(128, 1)
void k1_gemm_relu_q(const float* __restrict__ x, const float* __restrict__ W1,
                    const float* __restrict__ b1, const float* __restrict__ W2,
                    const float* __restrict__ b2)
{
    float* Xs = (float*)smem_raw;                       // [2][BK][XS_STRIDE]
    float* Ws = (float*)(smem_raw + 2 * XS_BUF * 4);    // [2][BK][WS_STRIDE]

    const int tid  = threadIdx.x;
    const int lane = tid & 31;
    const int w    = tid >> 5;
    const int wr   = w >> 1;         // 0..1 (token rows)
    const int wc   = w & 1;          // 0..1 (col halves)
    const int tr   = lane >> 3;      // 0..3
    const int cg   = lane & 7;       // 0..7
    const int t0   = blockIdx.x * BM;

    const int tokb = (wr << 5) + (tr << 3);   // lane's 8 tokens
    const int colb = (wc << 6) + (cg << 3);   // lane's 8 cols

    // Loader mapping (conflict-free STS: whole rows per warp)
    const int xt  = tid & 63;           // X token
    const int xkq = (tid >> 6) << 3;    // X k-offset: 0 or 8
    const int wcA = tid;                // W col 0..127 (full k row per thread)

    const float* xp = x  + (size_t)(t0 + xt) * D_IN + xkq;
    const float* wp = W1 + (size_t)wcA * D_IN;

    unsigned long long acc[8][4];
#pragma unroll
    for (int t = 0; t < 8; t++)
#pragma unroll
        for (int c = 0; c < 4; c++) acc[t][c] = 0ull;

    float4 px0, px1, pw0, pw1, pw2, pw3;
    px0 = *(const float4*)(xp);
    px1 = *(const float4*)(xp + 4);
    pw0 = *(const float4*)(wp);
    pw1 = *(const float4*)(wp + 4);
    pw2 = *(const float4*)(wp + 8);
    pw3 = *(const float4*)(wp + 12);

#define STORE_TILE(buf)                                                        \
    do {                                                                       \
        float* xb = Xs + (buf) * XS_BUF;                                       \
        float* wb = Ws + (buf) * WS_BUF;                                       \
        xb[(xkq + 0) * XS_STRIDE + xt] = px0.x;                                \
        xb[(xkq + 1) * XS_STRIDE + xt] = px0.y;                                \
        xb[(xkq + 2) * XS_STRIDE + xt] = px0.z;                                \
        xb[(xkq + 3) * XS_STRIDE + xt] = px0.w;                                \
        xb[(xkq + 4) * XS_STRIDE + xt] = px1.x;                                \
        xb[(xkq + 5) * XS_STRIDE + xt] = px1.y;                                \
        xb[(xkq + 6) * XS_STRIDE + xt] = px1.z;                                \
        xb[(xkq + 7) * XS_STRIDE + xt] = px1.w;                                \
        wb[ 0 * WS_STRIDE + wcA] = pw0.x;                                      \
        wb[ 1 * WS_STRIDE + wcA] = pw0.y;                                      \
        wb[ 2 * WS_STRIDE + wcA] = pw0.z;                                      \
        wb[ 3 * WS_STRIDE + wcA] = pw0.w;                                      \
        wb[ 4 * WS_STRIDE + wcA] = pw1.x;                                      \
        wb[ 5 * WS_STRIDE + wcA] = pw1.y;                                      \
        wb[ 6 * WS_STRIDE + wcA] = pw1.z;                                      \
        wb[ 7 * WS_STRIDE + wcA] = pw1.w;                                      \
        wb[ 8 * WS_STRIDE + wcA] = pw2.x;                                      \
        wb[ 9 * WS_STRIDE + wcA] = pw2.y;                                      \
        wb[10 * WS_STRIDE + wcA] = pw2.z;                                      \
        wb[11 * WS_STRIDE + wcA] = pw2.w;                                      \
        wb[12 * WS_STRIDE + wcA] = pw3.x;                                      \
        wb[13 * WS_STRIDE + wcA] = pw3.y;                                      \
        wb[14 * WS_STRIDE + wcA] = pw3.z;                                      \
        wb[15 * WS_STRIDE + wcA] = pw3.w;                                      \
    } while (0)

    STORE_TILE(0);
    __syncthreads();

#pragma unroll 1
    for (int kt = 0; kt < NKT; kt++) {
        const int cur = kt & 1;
        if (kt < NKT - 1) {
            const int k0 = (kt + 1) * BK;
            px0 = *(const float4*)(xp + k0);
            px1 = *(const float4*)(xp + k0 + 4);
            pw0 = *(const float4*)(wp + k0);
            pw1 = *(const float4*)(wp + k0 + 4);
            pw2 = *(const float4*)(wp + k0 + 8);
            pw3 = *(const float4*)(wp + k0 + 12);
        }
        const float* xb = Xs + cur * XS_BUF;
        const float* wb = Ws + cur * WS_BUF;
#pragma unroll
        for (int k = 0; k < BK; k++) {
            const float4 a0 = *(const float4*)&xb[k * XS_STRIDE + tokb];
            const float4 a1 = *(const float4*)&xb[k * XS_STRIDE + tokb + 4];
            const ulonglong2 b01 = *(const ulonglong2*)&wb[k * WS_STRIDE + colb];
            const ulonglong2 b23 = *(const ulonglong2*)&wb[k * WS_STRIDE + colb + 4];
            unsigned long long d0, d1, d2, d3, d4, d5, d6, d7;
            DUP2(d0, a0.x); DUP2(d1, a0.y); DUP2(d2, a0.z); DUP2(d3, a0.w);
            DUP2(d4, a1.x); DUP2(d5, a1.y); DUP2(d6, a1.z); DUP2(d7, a1.w);
            FMA2(acc[0][0], d0, b01.x); FMA2(acc[0][1], d0, b01.y);
            FMA2(acc[0][2], d0, b23.x); FMA2(acc[0][3], d0, b23.y);
            FMA2(acc[1][0], d1, b01.x); FMA2(acc[1][1], d1, b01.y);
            FMA2(acc[1][2], d1, b23.x); FMA2(acc[1][3], d1, b23.y);
            FMA2(acc[2][0], d2, b01.x); FMA2(acc[2][1], d2, b01.y);
            FMA2(acc[2][2], d2, b23.x); FMA2(acc[2][3], d2, b23.y);
            FMA2(acc[3][0], d3, b01.x); FMA2(acc[3][1], d3, b01.y);
            FMA2(acc[3][2], d3, b23.x); FMA2(acc[3][3], d3, b23.y);
            FMA2(acc[4][0], d4, b01.x); FMA2(acc[4][1], d4, b01.y);
            FMA2(acc[4][2], d4, b23.x); FMA2(acc[4][3], d4, b23.y);
            FMA2(acc[5][0], d5, b01.x); FMA2(acc[5][1], d5, b01.y);
            FMA2(acc[5][2], d5, b23.x); FMA2(acc[5][3], d5, b23.y);
            FMA2(acc[6][0], d6, b01.x); FMA2(acc[6][1], d6, b01.y);
            FMA2(acc[6][2], d6, b23.x); FMA2(acc[6][3], d6, b23.y);
            FMA2(acc[7][0], d7, b01.x); FMA2(acc[7][1], d7, b01.y);
            FMA2(acc[7][2], d7, b23.x); FMA2(acc[7][3], d7, b23.y);
        }
        if (kt < NKT - 1) STORE_TILE(cur ^ 1);
        __syncthreads();
    }

    // ---------------- Epilogue: bias+relu -> hs (smem), then q ----------------
    float* hs  = (float*)smem_raw;                               // [64][HS_STRIDE]
    float* W2s = (float*)(smem_raw + BM * HS_STRIDE * 4);        // W2^T [128][32]

    const float4 bA = __ldg((const float4*)(b1 + colb));
    const float4 bB = __ldg((const float4*)(b1 + colb + 4));
#pragma unroll
    for (int t = 0; t < 8; t++) {
        float4 lo, hi;
        lo.x = __uint_as_float((unsigned)(acc[t][0]))       + bA.x;
        lo.y = __uint_as_float((unsigned)(acc[t][0] >> 32)) + bA.y;
        lo.z = __uint_as_float((unsigned)(acc[t][1]))       + bA.z;
        lo.w = __uint_as_float((unsigned)(acc[t][1] >> 32)) + bA.w;
        hi.x = __uint_as_float((unsigned)(acc[t][2]))       + bB.x;
        hi.y = __uint_as_float((unsigned)(acc[t][2] >> 32)) + bB.y;
        hi.z = __uint_as_float((unsigned)(acc[t][3]))       + bB.z;
        hi.w = __uint_as_float((unsigned)(acc[t][3] >> 32)) + bB.w;
        lo.x = fmaxf(lo.x, 0.f); lo.y = fmaxf(lo.y, 0.f);
        lo.z = fmaxf(lo.z, 0.f); lo.w = fmaxf(lo.w, 0.f);
        hi.x = fmaxf(hi.x, 0.f); hi.y = fmaxf(hi.y, 0.f);
        hi.z = fmaxf(hi.z, 0.f); hi.w = fmaxf(hi.w, 0.f);
        *(float4*)&hs[(tokb + t) * HS_STRIDE + colb]     = lo;
        *(float4*)&hs[(tokb + t) * HS_STRIDE + colb + 4] = hi;
    }

    // W2^T into smem: W2 is [c][j]; store W2s[j*32 + c]
#pragma unroll
    for (int idx = tid; idx < QDIM * H1; idx += 128) {
        const int c = idx >> 7, j = idx & 127;
        W2s[j * QDIM + c] = W2[idx];
    }
    __syncthreads();

    // q: thread -> token tid>>1, 16 q-dims (tid&1)*16.. ; j ascending
    // (per-dim fmaf order identical to prior rounds; FMA2 is per-lane exact)
    {
        const int tok = tid >> 1;
        const int qg  = (tid & 1) << 4;
        unsigned long long q[8];
        {
            const ulonglong2 bq0 = *(const ulonglong2*)(b2 + qg);
            const ulonglong2 bq1 = *(const ulonglong2*)(b2 + qg + 4);
            const ulonglong2 bq2 = *(const ulonglong2*)(b2 + qg + 8);
            const ulonglong2 bq3 = *(const ulonglong2*)(b2 + qg + 12);
            q[0] = bq0.x; q[1] = bq0.y; q[2] = bq1.x; q[3] = bq1.y;
            q[4] = bq2.x; q[5] = bq2.y; q[6] = bq3.x; q[7] = bq3.y;
        }
#pragma unroll 8
        for (int j = 0; j < H1; j++) {
            const float hv = hs[tok * HS_STRIDE + j];
            unsigned long long hd;
            DUP2(hd, hv);
            const ulonglong2 w01 = *(const ulonglong2*)&W2s[j * QDIM + qg];
            const ulonglong2 w23 = *(const ulonglong2*)&W2s[j * QDIM + qg + 4];
            const ulonglong2 w45 = *(const ulonglong2*)&W2s[j * QDIM + qg + 8];
            const ulonglong2 w67 = *(const ulonglong2*)&W2s[j * QDIM + qg + 12];
            FMA2(q[0], hd, w01.x); FMA2(q[1], hd, w01.y);
            FMA2(q[2], hd, w23.x); FMA2(q[3], hd, w23.y);
            FMA2(q[4], hd, w45.x); FMA2(q[5], hd, w45.y);
            FMA2(q[6], hd, w67.x); FMA2(q[7], hd, w67.y);
        }
        ulonglong2* op = (ulonglong2*)&g_q[(size_t)(t0 + tok) * QDIM + qg];
        op[0] = make_ulonglong2(q[0], q[1]);
        op[1] = make_ulonglong2(q[2], q[3]);
        op[2] = make_ulonglong2(q[4], q[5]);
        op[3] = make_ulonglong2(q[6], q[7]);
    }
}

// ---------------------------------------------------------------------------
// Kernel 3: scores + top-k + combine + softmax.
// 2 warps per token (warp = one head). All staging in registers; kill uses
// unrolled predicated compares (no dynamic register indexing -> no local mem).
// Comparator identical to before: (v greater) or (v equal and idx lower).
// ---------------------------------------------------------------------------
__global__ __launch_bounds__(256, 1)
void k3_topk(const float* __restrict__ keys)
{
    __shared__ float ks[2 * 2 * NKEYS * HALFD];   // 32 KB

    const int tid = threadIdx.x;
    for (int i = tid; i < 2 * 2 * NKEYS * HALFD; i += 256) ks[i] = keys[i];
    __syncthreads();

    const int w    = tid >> 5;
    const int lane = tid & 31;
    const int t    = blockIdx.x * 4 + (w >> 1);
    const int hw   = w & 1;                      // this warp's head
    const float myq = g_q[(size_t)t * QDIM + lane];
    const float NEGINF = __uint_as_float(0xff800000u);

    // Per-lane staged results (predicated saves; every slot covered by rounds)
    float my_sc1 = NEGINF, my_sc1b = NEGINF, my_sc2 = NEGINF;
    int   my_id1 = 0, my_id1b = 0, my_id2 = 0;

    const int a_lo = lane >> 3;        // 0..3
    const int a_hi = a_lo + 4;         // 4..7
    const int b_ix = lane & 7;         // 0..7

#pragma unroll
    for (int side = 0; side < 2; side++) {
        const int u = hw * 2 + side;
        float qv[HALFD];
#pragma unroll
        for (int c = 0; c < HALFD; c++)
            qv[c] = __shfl_sync(0xffffffffu, myq, hw * 16 + side * 8 + c);

        float s[8];
#pragma unroll
        for (int i = 0; i < 8; i++) {
            const int n = i * 32 + lane;
            const float4 k0 = *(const float4*)&ks[(u * NKEYS + n) * HALFD];
            const float4 k1 = *(const float4*)&ks[(u * NKEYS + n) * HALFD + 4];
            s[i] = qv[0] * k0.x + qv[1] * k0.y + qv[2] * k0.z + qv[3] * k0.w
                 + qv[4] * k1.x + qv[5] * k1.y + qv[6] * k1.z + qv[7] * k1.w;
        }
#pragma unroll
        for (int r = 0; r < KNN; r++) {
            float bv = NEGINF; int bn = 0x7fffffff;
#pragma unroll
            for (int i = 0; i < 8; i++)
                if (s[i] > bv) { bv = s[i]; bn = i * 32 + lane; }
#pragma unroll
            for (int off = 16; off; off >>= 1) {
                const float ov = __shfl_xor_sync(0xffffffffu, bv, off);
                const int   on = __shfl_xor_sync(0xffffffffu, bn, off);
                if (ov > bv || (ov == bv && on < bn)) { bv = ov; bn = on; }
            }
            // stage into registers (all lanes hold the winner after butterfly)
            if (side == 0) {
                if (a_lo == r) { my_sc1  = bv; my_id1  = bn; }
                if (a_hi == r) { my_sc1b = bv; my_id1b = bn; }
            } else {
                if (b_ix == r) { my_sc2  = bv; my_id2  = bn; }
            }
            // kill winner — unrolled predicated (keeps s[] in registers)
#pragma unroll
            for (int i = 0; i < 8; i++)
                if (bn == i * 32 + lane) s[i] = NEGINF;
        }
    }

    // ---- Combine: 64 combos (lane holds c=lane and c=lane+32), top-8 ----
    float v0 = my_sc1  + my_sc2;
    float v1 = my_sc1b + my_sc2;
    const int idc0 = my_id1  * NKEYS + my_id2;
    const int idc1 = my_id1b * NKEYS + my_id2;

    float fsc[KNN];
    int   fid[KNN];
#pragma unroll
    for (int r = 0; r < KNN; r++) {
        float bv = v0; int bc = lane;
        if (v1 > bv) { bv = v1; bc = lane + 32; }
#pragma unroll
        for (int off = 16; off; off >>= 1) {
            const float ov = __shfl_xor_sync(0xffffffffu, bv, off);
            const int   oc = __shfl_xor_sync(0xffffffffu, bc, off);
            if (ov > bv || (ov == bv && oc < bc)) { bv = ov; bc = oc; }
        }
        const int idsel = (bc < 32) ? idc0 : idc1;
        fid[r] = __shfl_sync(0xffffffffu, idsel, bc & 31);
        fsc[r] = bv;
        if (bc == lane)      v0 = NEGINF;
        if (bc == lane + 32) v1 = NEGINF;
    }

    // ---- softmax over the 8 (computed redundantly on all lanes) ----
    float m = fsc[0];
#pragma unroll
    for (int i = 1; i < KNN; i++) m = fmaxf(m, fsc[i]);
    float e[KNN];
    float den = 0.f;
#pragma unroll
    for (int i = 0; i < KNN; i++) { e[i] = __expf(fsc[i] - m); den += e[i]; }
    const float inv = 1.0f / den;

#pragma unroll
    for (int r = 0; r < KNN; r++) {
        if (lane == r) {
            g_wt[t * 16 + hw * 8 + r] = e[r] * inv;
            g_id[t * 16 + hw * 8 + r] = fid[r];
        }
    }
}

// ---------------------------------------------------------------------------
// Kernel 4: out[t] = sum_{k<16} w_k * values[idx_k]  (proven ~53us)
// ---------------------------------------------------------------------------
__global__ __launch_bounds__(256, 1)
void k4_gather(const float* __restrict__ values, float* __restrict__ out)
{
    __shared__ float ws[16];
    __shared__ int   is[16];
    const int t = blockIdx.x;
    if (threadIdx.x < 16) {
        ws[threadIdx.x] = g_wt[t * 16 + threadIdx.x];
        is[threadIdx.x] = g_id[t * 16 + threadIdx.x];
    }
    __syncthreads();
    const int col = threadIdx.x << 2;
    float4 acc = make_float4(0.f, 0.f, 0.f, 0.f);
#pragma unroll
    for (int k = 0; k < 16; k++) {
        const float4 v = __ldg((const float4*)(values + (size_t)is[k] * D_IN + col));
        const float wk = ws[k];
        acc.x = fmaf(wk, v.x, acc.x);
        acc.y = fmaf(wk, v.y, acc.y);
        acc.z = fmaf(wk, v.z, acc.z);
        acc.w = fmaf(wk, v.w, acc.w);
    }
    *(float4*)(out + (size_t)t * D_IN + col) = acc;
}

// ---------------------------------------------------------------------------
extern "C" void kernel_launch(void* const* d_in, const int* in_sizes, int n_in,
                              void* d_out, int out_size)
{
    const float* x      = (const float*)d_in[0];
    const float* W1     = (const float*)d_in[1];
    const float* b1     = (const float*)d_in[2];
    const float* W2     = (const float*)d_in[3];
    const float* b2     = (const float*)d_in[4];
    const float* keys   = (const float*)d_in[5];
    const float* values = (const float*)d_in[6];
    float* out = (float*)d_out;

    cudaFuncSetAttribute(k1_gemm_relu_q,
                         cudaFuncAttributeMaxDynamicSharedMemorySize, SMEM_BYTES);

    k1_gemm_relu_q<<<T_TOK / BM, 128, SMEM_BYTES>>>(x, W1, b1, W2, b2);
    k3_topk<<<T_TOK / 4, 256>>>(keys);
    k4_gather<<<T_TOK, 256>>>(values, out);
}